// round 1
// baseline (speedup 1.0000x reference)
#include <cuda_runtime.h>
#include <math.h>

// Problem constants
#define NB 2
#define NS 4096
#define NV 50257
#define NH 1024
#define MASKID 50256
#define TPB 256
#define NROWS (NB * NS)   // 8192

__global__ __launch_bounds__(TPB)
void softmask_kernel(const void* __restrict__ x_t_raw,
                     const float* __restrict__ probs,
                     const float* __restrict__ embed,
                     const float* __restrict__ p_os,
                     const float* __restrict__ p_oa,
                     const float* __restrict__ p_ob,
                     float* __restrict__ out)
{
    const int row = blockIdx.x;
    const int tid = threadIdx.x;

    // ---- dtype-width detection for x_t (int64 vs int32) ----
    // int64 nonneg tokens => every odd 32-bit word of the first 32 elements is 0.
    // int32 random tokens => some odd word nonzero with overwhelming probability.
    __shared__ long long s_tok;
    if (tid == 0) {
        const int* xi = (const int*)x_t_raw;
        bool is64 = true;
        #pragma unroll
        for (int k = 1; k < 64; k += 2) {
            if (xi[k] != 0) { is64 = false; break; }
        }
        long long tok;
        if (is64) tok = ((const long long*)x_t_raw)[row];
        else      tok = (long long)xi[row];
        s_tok = tok;
    }
    __syncthreads();
    const long long tok = s_tok;

    float4* orow = (float4*)(out + (size_t)row * NH);

    if (tok != (long long)MASKID) {
        // ---- fast path: output = embed_table[tok] ----
        const float4* erow = (const float4*)(embed + (size_t)tok * NH);
        orow[tid] = erow[tid];            // 256 threads x float4 = 1024 floats
        return;
    }

    // ---- rare heavy path: top-3 + entropy over the vocab row ----
    __shared__ float sv[TPB * 3];
    __shared__ int   si[TPB * 3];
    __shared__ float sent[TPB];
    __shared__ float bw[3];
    __shared__ int   bidx[3];
    __shared__ float blam;

    const float* p = probs + (size_t)row * NV;

    float v0 = -1e30f, v1 = -1e30f, v2 = -1e30f;
    int   i0 = 0, i1 = 0, i2 = 0;
    float ent = 0.0f;

    for (int i = tid; i < NV; i += TPB) {
        float v = p[i];
        if (v > 0.0f) ent -= v * __logf(v);
        if (v > v0)      { v2 = v1; i2 = i1; v1 = v0; i1 = i0; v0 = v; i0 = i; }
        else if (v > v1) { v2 = v1; i2 = i1; v1 = v;  i1 = i; }
        else if (v > v2) { v2 = v;  i2 = i; }
    }

    sv[tid * 3 + 0] = v0; si[tid * 3 + 0] = i0;
    sv[tid * 3 + 1] = v1; si[tid * 3 + 1] = i1;
    sv[tid * 3 + 2] = v2; si[tid * 3 + 2] = i2;
    sent[tid] = ent;
    __syncthreads();

    // entropy tree reduce
    for (int off = TPB / 2; off > 0; off >>= 1) {
        if (tid < off) sent[tid] += sent[tid + off];
        __syncthreads();
    }

    if (tid == 0) {
        // merge 768 (value,index) candidates -> global top-3
        float m0 = -1e30f, m1 = -1e30f, m2 = -1e30f;
        int   j0 = 0, j1 = 0, j2 = 0;
        for (int k = 0; k < TPB * 3; ++k) {
            float v  = sv[k];
            int   ix = si[k];
            if (v > m0)      { m2 = m1; j2 = j1; m1 = m0; j1 = j0; m0 = v; j0 = ix; }
            else if (v > m1) { m2 = m1; j2 = j1; m1 = v;  j1 = ix; }
            else if (v > m2) { m2 = v;  j2 = ix; }
        }
        float ssum = m0 + m1 + m2 + 1e-10f;
        bw[0] = m0 / ssum;  bw[1] = m1 / ssum;  bw[2] = m2 / ssum;
        bidx[0] = j0;       bidx[1] = j1;       bidx[2] = j2;

        float os = p_os[0], oa = p_oa[0], ob = p_ob[0];
        float sp_oa = (oa > 20.0f) ? oa : log1pf(expf(oa));
        float sp_ob = (ob > 20.0f) ? ob : log1pf(expf(ob));
        float entropy = sent[0];
        float sig_os = 1.0f / (1.0f + expf(-os));
        // lam = sigmoid(os) * sigmoid(softplus(oa) * (softplus(ob) - entropy))
        float arg = sp_oa * (sp_ob - entropy);
        blam = sig_os * (1.0f / (1.0f + expf(-arg)));
    }
    __syncthreads();

    const float w0 = bw[0], w1 = bw[1], w2 = bw[2];
    const float lam = blam;
    const float4* e0 = (const float4*)(embed + (size_t)bidx[0] * NH);
    const float4* e1 = (const float4*)(embed + (size_t)bidx[1] * NH);
    const float4* e2 = (const float4*)(embed + (size_t)bidx[2] * NH);
    const float4* er = (const float4*)(embed + (size_t)MASKID  * NH);

    float4 a = e0[tid], b = e1[tid], c = e2[tid], r = er[tid];
    float4 o;
    o.x = (1.0f - lam) * r.x + lam * (w0 * a.x + w1 * b.x + w2 * c.x);
    o.y = (1.0f - lam) * r.y + lam * (w0 * a.y + w1 * b.y + w2 * c.y);
    o.z = (1.0f - lam) * r.z + lam * (w0 * a.z + w1 * b.z + w2 * c.z);
    o.w = (1.0f - lam) * r.w + lam * (w0 * a.w + w1 * b.w + w2 * c.w);
    orow[tid] = o;
}

extern "C" void kernel_launch(void* const* d_in, const int* in_sizes, int n_in,
                              void* d_out, int out_size)
{
    (void)in_sizes; (void)n_in; (void)out_size;
    const void*  x_t   = d_in[0];                 // int64 or int32, detected on device
    const float* probs = (const float*)d_in[1];   // (B, S, V)
    const float* embed = (const float*)d_in[2];   // (V, H)
    const float* om_s  = (const float*)d_in[3];
    const float* om_a  = (const float*)d_in[4];
    const float* om_b  = (const float*)d_in[5];
    float* out = (float*)d_out;                   // (B, S, H)

    softmask_kernel<<<NROWS, TPB>>>(x_t, probs, embed, om_s, om_a, om_b, out);
}

// round 2
// speedup vs baseline: 1.1633x; 1.1633x over previous
#include <cuda_runtime.h>
#include <math.h>

// Problem constants
#define NB 2
#define NS 4096
#define NV 50257
#define NH 1024
#define MASKID 50256
#define TPB 256
#define RPB 4                    // rows per block
#define NROWS (NB * NS)          // 8192
#define NBLK (NROWS / RPB)       // 2048

__device__ __forceinline__ void heavy_row(int row, int tid,
                                          const float* __restrict__ probs,
                                          const float* __restrict__ embed,
                                          const float* __restrict__ p_os,
                                          const float* __restrict__ p_oa,
                                          const float* __restrict__ p_ob,
                                          float* __restrict__ out)
{
    // Block-cooperative top-3 + entropy over the vocab row (rare path).
    __shared__ float sv[TPB * 3];
    __shared__ int   si[TPB * 3];
    __shared__ float sent[TPB];
    __shared__ float bw[3];
    __shared__ int   bidx[3];
    __shared__ float blam;

    const float* p = probs + (size_t)row * NV;

    float v0 = -1e30f, v1 = -1e30f, v2 = -1e30f;
    int   i0 = 0, i1 = 0, i2 = 0;
    float ent = 0.0f;

    for (int i = tid; i < NV; i += TPB) {
        float v = p[i];
        if (v > 0.0f) ent -= v * __logf(v);
        if (v > v0)      { v2 = v1; i2 = i1; v1 = v0; i1 = i0; v0 = v; i0 = i; }
        else if (v > v1) { v2 = v1; i2 = i1; v1 = v;  i1 = i; }
        else if (v > v2) { v2 = v;  i2 = i; }
    }

    sv[tid * 3 + 0] = v0; si[tid * 3 + 0] = i0;
    sv[tid * 3 + 1] = v1; si[tid * 3 + 1] = i1;
    sv[tid * 3 + 2] = v2; si[tid * 3 + 2] = i2;
    sent[tid] = ent;
    __syncthreads();

    for (int off = TPB / 2; off > 0; off >>= 1) {
        if (tid < off) sent[tid] += sent[tid + off];
        __syncthreads();
    }

    if (tid == 0) {
        float m0 = -1e30f, m1 = -1e30f, m2 = -1e30f;
        int   j0 = 0, j1 = 0, j2 = 0;
        for (int k = 0; k < TPB * 3; ++k) {
            float v  = sv[k];
            int   ix = si[k];
            if (v > m0)      { m2 = m1; j2 = j1; m1 = m0; j1 = j0; m0 = v; j0 = ix; }
            else if (v > m1) { m2 = m1; j2 = j1; m1 = v;  j1 = ix; }
            else if (v > m2) { m2 = v;  j2 = ix; }
        }
        float ssum = m0 + m1 + m2 + 1e-10f;
        bw[0] = m0 / ssum;  bw[1] = m1 / ssum;  bw[2] = m2 / ssum;
        bidx[0] = j0;       bidx[1] = j1;       bidx[2] = j2;

        float os = p_os[0], oa = p_oa[0], ob = p_ob[0];
        float sp_oa = (oa > 20.0f) ? oa : log1pf(expf(oa));
        float sp_ob = (ob > 20.0f) ? ob : log1pf(expf(ob));
        float entropy = sent[0];
        float sig_os = 1.0f / (1.0f + expf(-os));
        float arg = sp_oa * (sp_ob - entropy);
        blam = sig_os * (1.0f / (1.0f + expf(-arg)));
    }
    __syncthreads();

    const float w0 = bw[0], w1 = bw[1], w2 = bw[2];
    const float lam = blam;
    const float4* e0 = (const float4*)(embed + (size_t)bidx[0] * NH);
    const float4* e1 = (const float4*)(embed + (size_t)bidx[1] * NH);
    const float4* e2 = (const float4*)(embed + (size_t)bidx[2] * NH);
    const float4* er = (const float4*)(embed + (size_t)MASKID  * NH);
    float4* orow = (float4*)(out + (size_t)row * NH);

    float4 a = e0[tid], b = e1[tid], c = e2[tid], r = er[tid];
    float4 o;
    o.x = (1.0f - lam) * r.x + lam * (w0 * a.x + w1 * b.x + w2 * c.x);
    o.y = (1.0f - lam) * r.y + lam * (w0 * a.y + w1 * b.y + w2 * c.y);
    o.z = (1.0f - lam) * r.z + lam * (w0 * a.z + w1 * b.z + w2 * c.z);
    o.w = (1.0f - lam) * r.w + lam * (w0 * a.w + w1 * b.w + w2 * c.w);
    orow[tid] = o;
    __syncthreads();   // protect shared arrays before next masked row reuses them
}

__global__ __launch_bounds__(TPB)
void softmask_kernel(const void* __restrict__ x_t_raw,
                     const float* __restrict__ probs,
                     const float* __restrict__ embed,
                     const float* __restrict__ p_os,
                     const float* __restrict__ p_oa,
                     const float* __restrict__ p_ob,
                     float* __restrict__ out)
{
    const int base = blockIdx.x * RPB;
    const int tid  = threadIdx.x;

    // ---- per-thread dtype-width detection (no shared, no sync) ----
    // int64 nonneg tokens => odd 32-bit words are 0. Check 4 of them:
    // int32 false-positive prob ~ (2e-5)^4 — negligible (and inputs are fixed-seed).
    const int* xi = (const int*)x_t_raw;
    const bool is64 = (xi[1] == 0) & (xi[3] == 0) & (xi[5] == 0) & (xi[7] == 0);

    int toks[RPB];
#pragma unroll
    for (int j = 0; j < RPB; ++j) {
        int row = base + j;
        toks[j] = is64 ? (int)((const long long*)x_t_raw)[row] : xi[row];
    }

    bool anymask = false;
#pragma unroll
    for (int j = 0; j < RPB; ++j) anymask |= (toks[j] == MASKID);

    if (!anymask) {
        // ---- fast path: 4 independent gather-copies, front-batched loads (MLP=4) ----
        float4 v[RPB];
#pragma unroll
        for (int j = 0; j < RPB; ++j) {
            const float4* erow = (const float4*)(embed + (size_t)toks[j] * NH);
            v[j] = erow[tid];
        }
#pragma unroll
        for (int j = 0; j < RPB; ++j) {
            float4* orow = (float4*)(out + (size_t)(base + j) * NH);
            __stcs(&orow[tid], v[j]);    // streaming store: output never re-read
        }
        return;
    }

    // ---- rare path: per-row handling; tokens are uniform across the block,
    //      so branches are block-uniform and barriers inside heavy_row are safe.
#pragma unroll
    for (int j = 0; j < RPB; ++j) {
        int row = base + j;
        if (toks[j] != MASKID) {
            const float4* erow = (const float4*)(embed + (size_t)toks[j] * NH);
            float4* orow = (float4*)(out + (size_t)row * NH);
            __stcs(&orow[tid], erow[tid]);
        } else {
            heavy_row(row, tid, probs, embed, p_os, p_oa, p_ob, out);
        }
    }
}

extern "C" void kernel_launch(void* const* d_in, const int* in_sizes, int n_in,
                              void* d_out, int out_size)
{
    (void)in_sizes; (void)n_in; (void)out_size;
    const void*  x_t   = d_in[0];
    const float* probs = (const float*)d_in[1];
    const float* embed = (const float*)d_in[2];
    const float* om_s  = (const float*)d_in[3];
    const float* om_a  = (const float*)d_in[4];
    const float* om_b  = (const float*)d_in[5];
    float* out = (float*)d_out;

    softmask_kernel<<<NBLK, TPB>>>(x_t, probs, embed, om_s, om_a, om_b, out);
}

// round 3
// speedup vs baseline: 1.1910x; 1.0239x over previous
#include <cuda_runtime.h>
#include <math.h>

// Problem constants
#define NB 2
#define NS 4096
#define NV 50257
#define NH 1024
#define MASKID 50256
#define TPB 256
#define WPB 8                     // warps per block
#define NROWS (NB * NS)           // 8192
#define NBLK (NROWS / WPB)        // 1024
#define CPL 8                     // float4 chunks per lane (1024/4/32)

__device__ __forceinline__ void ins3(float v, int i,
                                     float& v0, int& i0,
                                     float& v1, int& i1,
                                     float& v2, int& i2)
{
    if (v > v0 || (v == v0 && i < i0)) {
        v2 = v1; i2 = i1; v1 = v0; i1 = i0; v0 = v; i0 = i;
    } else if (v > v1 || (v == v1 && i < i1)) {
        v2 = v1; i2 = i1; v1 = v; i1 = i;
    } else if (v > v2 || (v == v2 && i < i2)) {
        v2 = v; i2 = i;
    }
}

__global__ __launch_bounds__(TPB)
void softmask_kernel(const void* __restrict__ x_t_raw,
                     const float* __restrict__ probs,
                     const float* __restrict__ embed,
                     const float* __restrict__ p_os,
                     const float* __restrict__ p_oa,
                     const float* __restrict__ p_ob,
                     float* __restrict__ out)
{
    const int warp = threadIdx.x >> 5;
    const int lane = threadIdx.x & 31;
    const int row  = blockIdx.x * WPB + warp;

    // ---- dtype-width detection (int64 vs int32), branch-free broadcast loads ----
    const int* xi = (const int*)x_t_raw;
    const bool is64 = (xi[1] == 0) & (xi[3] == 0) & (xi[5] == 0) & (xi[7] == 0);

    const int tok = is64 ? (int)((const long long*)x_t_raw)[row] : xi[row];

    float4* orow = (float4*)(out + (size_t)row * NH);

    if (tok != MASKID) {
        // ---- fast path: warp copies embed_table[tok] (4 KB), 8 front-batched LDG.128 ----
        const float4* erow = (const float4*)(embed + (size_t)tok * NH);
        float4 v[CPL];
#pragma unroll
        for (int j = 0; j < CPL; ++j) v[j] = erow[lane + 32 * j];
#pragma unroll
        for (int j = 0; j < CPL; ++j) __stcs(&orow[lane + 32 * j], v[j]);
        return;
    }

    // ---- rare heavy path: warp-local top-3 + entropy over the vocab row ----
    const float* p = probs + (size_t)row * NV;

    float v0 = -1e30f, v1 = -1e30f, v2 = -1e30f;
    int   i0 = 0x7fffffff, i1 = 0x7fffffff, i2 = 0x7fffffff;
    float ent = 0.0f;

    for (int i = lane; i < NV; i += 32) {
        float v = p[i];
        if (v > 0.0f) ent -= v * __logf(v);
        ins3(v, i, v0, i0, v1, i1, v2, i2);
    }

    // warp reductions (no shared memory)
#pragma unroll
    for (int off = 16; off > 0; off >>= 1) {
        ent += __shfl_xor_sync(0xffffffffu, ent, off);
        float ov0 = __shfl_xor_sync(0xffffffffu, v0, off);
        float ov1 = __shfl_xor_sync(0xffffffffu, v1, off);
        float ov2 = __shfl_xor_sync(0xffffffffu, v2, off);
        int   oi0 = __shfl_xor_sync(0xffffffffu, i0, off);
        int   oi1 = __shfl_xor_sync(0xffffffffu, i1, off);
        int   oi2 = __shfl_xor_sync(0xffffffffu, i2, off);
        ins3(ov0, oi0, v0, i0, v1, i1, v2, i2);
        ins3(ov1, oi1, v0, i0, v1, i1, v2, i2);
        ins3(ov2, oi2, v0, i0, v1, i1, v2, i2);
    }
    // all lanes now hold identical global top-3 and entropy

    float ssum = v0 + v1 + v2 + 1e-10f;
    float w0 = v0 / ssum, w1 = v1 / ssum, w2 = v2 / ssum;

    float os = p_os[0], oa = p_oa[0], ob = p_ob[0];
    float sp_oa = (oa > 20.0f) ? oa : log1pf(expf(oa));
    float sp_ob = (ob > 20.0f) ? ob : log1pf(expf(ob));
    float sig_os = 1.0f / (1.0f + expf(-os));
    float arg = sp_oa * (sp_ob - ent);
    float lam = sig_os * (1.0f / (1.0f + expf(-arg)));

    const float4* e0 = (const float4*)(embed + (size_t)i0 * NH);
    const float4* e1 = (const float4*)(embed + (size_t)i1 * NH);
    const float4* e2 = (const float4*)(embed + (size_t)i2 * NH);
    const float4* er = (const float4*)(embed + (size_t)MASKID * NH);

#pragma unroll
    for (int j = 0; j < CPL; ++j) {
        int c = lane + 32 * j;
        float4 a = e0[c], b = e1[c], cc = e2[c], r = er[c];
        float4 o;
        o.x = (1.0f - lam) * r.x + lam * (w0 * a.x + w1 * b.x + w2 * cc.x);
        o.y = (1.0f - lam) * r.y + lam * (w0 * a.y + w1 * b.y + w2 * cc.y);
        o.z = (1.0f - lam) * r.z + lam * (w0 * a.z + w1 * b.z + w2 * cc.z);
        o.w = (1.0f - lam) * r.w + lam * (w0 * a.w + w1 * b.w + w2 * cc.w);
        __stcs(&orow[c], o);
    }
}

extern "C" void kernel_launch(void* const* d_in, const int* in_sizes, int n_in,
                              void* d_out, int out_size)
{
    (void)in_sizes; (void)n_in; (void)out_size;
    const void*  x_t   = d_in[0];
    const float* probs = (const float*)d_in[1];
    const float* embed = (const float*)d_in[2];
    const float* om_s  = (const float*)d_in[3];
    const float* om_a  = (const float*)d_in[4];
    const float* om_b  = (const float*)d_in[5];
    float* out = (float*)d_out;

    softmask_kernel<<<NBLK, TPB>>>(x_t, probs, embed, om_s, om_a, om_b, out);
}